// round 1
// baseline (speedup 1.0000x reference)
#include <cuda_runtime.h>
#include <math.h>

#define NMAX 50000
#define EMAX 800000
#define D 128

// ---------------- scratch (static device globals; no allocation) -------------
__device__ int   g_counts[NMAX];       // edge-only in-degree (self loop excluded)
__device__ int   g_offsets[NMAX];      // exclusive scan of counts
__device__ int   g_cursor[NMAX];       // fill cursors
__device__ int   g_bsums[256];         // scan partials
__device__ int   g_adj[EMAX];          // CSR adjacency: src lists grouped by dst
__device__ float g_dis[NMAX];          // rsqrt(deg)
__device__ float g_bufG[NMAX * D];     // g = dis * (H @ W)
__device__ float g_bufH[NMAX * D];     // layer activations

// ---------------- preprocessing ---------------------------------------------
__global__ void k_init(int n) {
    int i = blockIdx.x * blockDim.x + threadIdx.x;
    if (i < n) { g_counts[i] = 0; g_cursor[i] = 0; }
}

__global__ void k_count(const int* __restrict__ dst, int e) {
    int i = blockIdx.x * blockDim.x + threadIdx.x;
    if (i < e) atomicAdd(&g_counts[dst[i]], 1);
}

__global__ void k_dis(int n) {
    int i = blockIdx.x * blockDim.x + threadIdx.x;
    if (i < n) g_dis[i] = rsqrtf((float)(g_counts[i] + 1));   // +1 self loop
}

// Hillis-Steele block scan (1024), exclusive result per element + block sums
__global__ void k_scan1(int n) {
    __shared__ int sh[1024];
    int i = blockIdx.x * 1024 + threadIdx.x;
    int v = (i < n) ? g_counts[i] : 0;
    sh[threadIdx.x] = v;
    __syncthreads();
    for (int off = 1; off < 1024; off <<= 1) {
        int t = 0;
        if ((int)threadIdx.x >= off) t = sh[threadIdx.x - off];
        __syncthreads();
        sh[threadIdx.x] += t;
        __syncthreads();
    }
    if (i < n) g_offsets[i] = sh[threadIdx.x] - v;   // exclusive
    if (threadIdx.x == 1023) g_bsums[blockIdx.x] = sh[1023];
}

__global__ void k_scan2(int nb) {
    if (threadIdx.x == 0 && blockIdx.x == 0) {
        int run = 0;
        for (int b = 0; b < nb; b++) { int t = g_bsums[b]; g_bsums[b] = run; run += t; }
    }
}

__global__ void k_scan3(int n) {
    int i = blockIdx.x * blockDim.x + threadIdx.x;
    if (i < n) g_offsets[i] += g_bsums[i >> 10];
}

__global__ void k_fill(const int* __restrict__ src, const int* __restrict__ dst, int e) {
    int i = blockIdx.x * blockDim.x + threadIdx.x;
    if (i < e) {
        int d = dst[i];
        int p = atomicAdd(&g_cursor[d], 1);
        g_adj[g_offsets[d] + p] = src[i];
    }
}

// ---------------- fused GEMM + dis scale:  G = diag(dis) * (A @ W) -----------
// 128x128 output tile per block, 256 threads, 8x8 micro-tile, K chunked by 8.
__global__ void k_gemm_scale(const float* __restrict__ A,
                             const float* __restrict__ W,
                             float* __restrict__ G, int n) {
    __shared__ float As[8][128];   // As[k][row]
    __shared__ float Bs[8][128];   // Bs[k][col]

    int row0 = blockIdx.x * 128;
    int tid  = threadIdx.x;                 // 0..255
    int tr   = (tid >> 4) << 3;             // thread row base 0..120
    int tc   = (tid & 15) << 3;             // thread col base 0..120

    float acc[8][8];
#pragma unroll
    for (int i = 0; i < 8; i++)
#pragma unroll
        for (int j = 0; j < 8; j++) acc[i][j] = 0.f;

    // global load mapping
    int a_row = tid >> 1;              // 0..127
    int a_seg = (tid & 1) << 2;        // 0 or 4 (k offset, float4)
    int b_kr  = tid >> 5;              // 0..7
    int b_c4  = (tid & 31) << 2;       // 0..124

    for (int kk = 0; kk < 128; kk += 8) {
        // A tile: 128 rows x 8 k
        float4 av = make_float4(0.f, 0.f, 0.f, 0.f);
        if (row0 + a_row < n)
            av = *(const float4*)&A[(size_t)(row0 + a_row) * D + kk + a_seg];
        As[a_seg + 0][a_row] = av.x;
        As[a_seg + 1][a_row] = av.y;
        As[a_seg + 2][a_row] = av.z;
        As[a_seg + 3][a_row] = av.w;
        // W tile: 8 k rows x 128 cols
        float4 wv = *(const float4*)&W[(size_t)(kk + b_kr) * D + b_c4];
        Bs[b_kr][b_c4 + 0] = wv.x;
        Bs[b_kr][b_c4 + 1] = wv.y;
        Bs[b_kr][b_c4 + 2] = wv.z;
        Bs[b_kr][b_c4 + 3] = wv.w;
        __syncthreads();

#pragma unroll
        for (int k = 0; k < 8; k++) {
            float a[8], b[8];
#pragma unroll
            for (int i = 0; i < 8; i++) a[i] = As[k][tr + i];
#pragma unroll
            for (int j = 0; j < 8; j++) b[j] = Bs[k][tc + j];
#pragma unroll
            for (int i = 0; i < 8; i++)
#pragma unroll
                for (int j = 0; j < 8; j++) acc[i][j] = fmaf(a[i], b[j], acc[i][j]);
        }
        __syncthreads();
    }

#pragma unroll
    for (int i = 0; i < 8; i++) {
        int row = row0 + tr + i;
        if (row < n) {
            float ds = g_dis[row];
            float4 o0 = make_float4(ds * acc[i][0], ds * acc[i][1], ds * acc[i][2], ds * acc[i][3]);
            float4 o1 = make_float4(ds * acc[i][4], ds * acc[i][5], ds * acc[i][6], ds * acc[i][7]);
            *(float4*)&G[(size_t)row * D + tc + 0] = o0;
            *(float4*)&G[(size_t)row * D + tc + 4] = o1;
        }
    }
}

// ---------------- neighbor aggregation (one warp per node) -------------------
// out[d] = dis[d] * ( sum_{s in adj(d)} g[s] + g[d] ) + b  [; relu]
__global__ void k_aggregate(const float* __restrict__ G,
                            const float* __restrict__ bias,
                            float* __restrict__ out, int n, int applyRelu) {
    int warp = (blockIdx.x * blockDim.x + threadIdx.x) >> 5;
    if (warp >= n) return;
    int lane = threadIdx.x & 31;

    const float4* G4 = (const float4*)G;
    float4 acc = G4[(size_t)warp * 32 + lane];    // self term
    int start = g_offsets[warp];
    int cnt   = g_counts[warp];

    int e = 0;
    for (; e + 4 <= cnt; e += 4) {
        int s0 = g_adj[start + e + 0];
        int s1 = g_adj[start + e + 1];
        int s2 = g_adj[start + e + 2];
        int s3 = g_adj[start + e + 3];
        float4 v0 = G4[(size_t)s0 * 32 + lane];
        float4 v1 = G4[(size_t)s1 * 32 + lane];
        float4 v2 = G4[(size_t)s2 * 32 + lane];
        float4 v3 = G4[(size_t)s3 * 32 + lane];
        acc.x += v0.x + v1.x + v2.x + v3.x;
        acc.y += v0.y + v1.y + v2.y + v3.y;
        acc.z += v0.z + v1.z + v2.z + v3.z;
        acc.w += v0.w + v1.w + v2.w + v3.w;
    }
    for (; e < cnt; e++) {
        int s = g_adj[start + e];
        float4 v = G4[(size_t)s * 32 + lane];
        acc.x += v.x; acc.y += v.y; acc.z += v.z; acc.w += v.w;
    }

    float ds = g_dis[warp];
    float4 b4 = ((const float4*)bias)[lane];
    float4 o;
    o.x = fmaf(ds, acc.x, b4.x);
    o.y = fmaf(ds, acc.y, b4.y);
    o.z = fmaf(ds, acc.z, b4.z);
    o.w = fmaf(ds, acc.w, b4.w);
    if (applyRelu) {
        o.x = fmaxf(o.x, 0.f); o.y = fmaxf(o.y, 0.f);
        o.z = fmaxf(o.z, 0.f); o.w = fmaxf(o.w, 0.f);
    }
    ((float4*)out)[(size_t)warp * 32 + lane] = o;
}

// ---------------- launch -----------------------------------------------------
extern "C" void kernel_launch(void* const* d_in, const int* in_sizes, int n_in,
                              void* d_out, int out_size) {
    const float* x  = (const float*)d_in[0];
    const int*   ei = (const int*)d_in[1];
    const float* W0 = (const float*)d_in[2];
    const float* b0 = (const float*)d_in[3];
    const float* W1 = (const float*)d_in[4];
    const float* b1 = (const float*)d_in[5];
    const float* W2 = (const float*)d_in[6];
    const float* b2 = (const float*)d_in[7];

    int n = in_sizes[0] / D;
    int e = in_sizes[1] / 2;
    const int* src = ei;
    const int* dst = ei + e;

    float* bufG = nullptr; float* bufH = nullptr;
    cudaGetSymbolAddress((void**)&bufG, g_bufG);
    cudaGetSymbolAddress((void**)&bufH, g_bufH);
    float* out = (float*)d_out;

    int gn  = (n + 255) / 256;
    int ge  = (e + 255) / 256;
    int nb  = (n + 1023) / 1024;

    // preprocessing: degrees, dis, CSR
    k_init <<<gn, 256>>>(n);
    k_count<<<ge, 256>>>(dst, e);
    k_dis  <<<gn, 256>>>(n);
    k_scan1<<<nb, 1024>>>(n);
    k_scan2<<<1, 32>>>(nb);
    k_scan3<<<gn, 256>>>(n);
    k_fill <<<ge, 256>>>(src, dst, e);

    int ggemm = (n + 127) / 128;
    int gagg  = (n * 32 + 255) / 256;   // one warp per node, 8 warps/block

    // layer 0
    k_gemm_scale<<<ggemm, 256>>>(x, W0, bufG, n);
    k_aggregate <<<gagg, 256>>>(bufG, b0, bufH, n, 1);
    // layer 1
    k_gemm_scale<<<ggemm, 256>>>(bufH, W1, bufG, n);
    k_aggregate <<<gagg, 256>>>(bufG, b1, bufH, n, 1);
    // layer 2 (no relu, write to d_out)
    k_gemm_scale<<<ggemm, 256>>>(bufH, W2, bufG, n);
    k_aggregate <<<gagg, 256>>>(bufG, b2, out, n, 0);
}

// round 4
// speedup vs baseline: 1.3652x; 1.3652x over previous
#include <cuda_runtime.h>
#include <cuda_bf16.h>
#include <math.h>
#include <stdint.h>

#define NMAX 50000
#define EMAX 800000
#define D 128

// ---------------- scratch (static device globals; no allocation) -------------
__device__ int   g_counts[NMAX];
__device__ int   g_offsets[NMAX];
__device__ int   g_cursor[NMAX];
__device__ int   g_bsums[256];
__device__ int   g_adj[EMAX];
__device__ float g_dis[NMAX];
__device__ float g_bufG[NMAX * D];
__device__ float g_bufH[NMAX * D];
__device__ __nv_bfloat16 g_WtHi[3][D * D];   // W transposed [n][k], hi part
__device__ __nv_bfloat16 g_WtLo[3][D * D];   // residual lo part

// ---------------- PTX helpers (sm_80-era: mma.sync + ldmatrix) ---------------
__device__ __forceinline__ uint32_t smem_u32(const void* p) {
    uint32_t a;
    asm("{ .reg .u64 t; cvta.to.shared.u64 t, %1; cvt.u32.u64 %0, t; }" : "=r"(a) : "l"(p));
    return a;
}

__device__ __forceinline__ void ldsm_x4(uint32_t* r, uint32_t addr) {
    asm volatile("ldmatrix.sync.aligned.m8n8.x4.shared.b16 {%0,%1,%2,%3}, [%4];"
        : "=r"(r[0]), "=r"(r[1]), "=r"(r[2]), "=r"(r[3]) : "r"(addr));
}

__device__ __forceinline__ void mma_bf16(float* c, const uint32_t* a, uint32_t b0, uint32_t b1) {
    asm volatile(
        "mma.sync.aligned.m16n8k16.row.col.f32.bf16.bf16.f32 "
        "{%0,%1,%2,%3}, {%4,%5,%6,%7}, {%8,%9}, {%0,%1,%2,%3};"
        : "+f"(c[0]), "+f"(c[1]), "+f"(c[2]), "+f"(c[3])
        : "r"(a[0]), "r"(a[1]), "r"(a[2]), "r"(a[3]), "r"(b0), "r"(b1));
}

// ---------------- preprocessing ---------------------------------------------
__global__ void k_count(const int* __restrict__ dst, int e) {
    int i = blockIdx.x * blockDim.x + threadIdx.x;
    if (i < e) atomicAdd(&g_counts[dst[i]], 1);
}

__global__ void k_scan1(int n) {
    __shared__ int sh[1024];
    int i = blockIdx.x * 1024 + threadIdx.x;
    int v = (i < n) ? g_counts[i] : 0;
    if (i < n) g_dis[i] = rsqrtf((float)(v + 1));   // +1 self loop
    sh[threadIdx.x] = v;
    __syncthreads();
    for (int off = 1; off < 1024; off <<= 1) {
        int t = 0;
        if ((int)threadIdx.x >= off) t = sh[threadIdx.x - off];
        __syncthreads();
        sh[threadIdx.x] += t;
        __syncthreads();
    }
    if (i < n) g_offsets[i] = sh[threadIdx.x] - v;
    if (threadIdx.x == 1023) g_bsums[blockIdx.x] = sh[1023];
}

__global__ void k_scan2(int nb) {
    if (threadIdx.x == 0 && blockIdx.x == 0) {
        int run = 0;
        for (int b = 0; b < nb; b++) { int t = g_bsums[b]; g_bsums[b] = run; run += t; }
    }
}

__global__ void k_scan3(int n) {
    int i = blockIdx.x * blockDim.x + threadIdx.x;
    if (i < n) g_offsets[i] += g_bsums[i >> 10];
}

__global__ void k_fill(const int* __restrict__ src, const int* __restrict__ dst, int e) {
    int i = blockIdx.x * blockDim.x + threadIdx.x;
    if (i < e) {
        int d = dst[i];
        int p = atomicAdd(&g_cursor[d], 1);
        g_adj[g_offsets[d] + p] = src[i];
    }
}

// ---------------- W transpose + bf16 split (once per layer) ------------------
__global__ void k_prep_w(const float* __restrict__ W,
                         __nv_bfloat16* __restrict__ hiOut,
                         __nv_bfloat16* __restrict__ loOut) {
    int nn = blockIdx.x;
    int k  = threadIdx.x;
    float v = W[k * D + nn];
    __nv_bfloat16 h = __float2bfloat16_rn(v);
    __nv_bfloat16 l = __float2bfloat16_rn(v - __bfloat162float(h));
    hiOut[nn * D + k] = h;
    loOut[nn * D + k] = l;
}

// ---------------- HMMA GEMM:  G = diag(dis) * (A @ W) ------------------------
// 128x128 block tile, 256 threads = 8 warps (4x2), warp tile 32x64.
// bf16 hi/lo split, 3 products: Ah@Wh + Ah@Wl + Al@Wh, fp32 accum.
// K chunked by 64 (2 chunks). SMEM tiles padded to 72 halves/row.
#define BK   64
#define PADK 72
#define SM_TILE (128 * PADK)              // halves per tile
#define GEMM_SMEM (4 * SM_TILE * 2)       // bytes: Ah, Al, Wh, Wl

__global__ void __launch_bounds__(256, 2) k_gemm_mma(
    const float* __restrict__ A,
    const __nv_bfloat16* __restrict__ WtHi,
    const __nv_bfloat16* __restrict__ WtLo,
    float* __restrict__ G, int n)
{
    extern __shared__ char smem[];
    __nv_bfloat16* sAh = (__nv_bfloat16*)smem;
    __nv_bfloat16* sAl = sAh + SM_TILE;
    __nv_bfloat16* sWh = sAl + SM_TILE;
    __nv_bfloat16* sWl = sWh + SM_TILE;

    int tid  = threadIdx.x;
    int lane = tid & 31;
    int w    = tid >> 5;
    int warp_m = w >> 1;          // 0..3
    int warp_n = w & 1;           // 0..1
    int m0 = warp_m * 32;
    int n0 = warp_n * 64;
    int row0 = blockIdx.x * 128;

    uint32_t aAh = smem_u32(sAh);
    uint32_t aAl = smem_u32(sAl);
    uint32_t aWh = smem_u32(sWh);
    uint32_t aWl = smem_u32(sWl);

    float acc[2][8][4];
#pragma unroll
    for (int mt = 0; mt < 2; mt++)
#pragma unroll
        for (int nt = 0; nt < 8; nt++)
#pragma unroll
            for (int q = 0; q < 4; q++) acc[mt][nt][q] = 0.f;

    // thread load mapping: 2 threads per row
    int ldRow = tid >> 1;
    int ldCol = (tid & 1) * 32;   // half-index base within chunk (32 halves)

    for (int kc = 0; kc < 2; kc++) {
        // ---- A chunk -> bf16 hi/lo ----
        bool okA = (row0 + ldRow) < n;
        const float4* Ar = (const float4*)(A + (size_t)(row0 + ldRow) * D + kc * BK + ldCol);
#pragma unroll
        for (int j = 0; j < 8; j++) {
            float4 v = okA ? Ar[j] : make_float4(0.f, 0.f, 0.f, 0.f);
            __nv_bfloat16 hx = __float2bfloat16_rn(v.x);
            __nv_bfloat16 hy = __float2bfloat16_rn(v.y);
            __nv_bfloat16 hz = __float2bfloat16_rn(v.z);
            __nv_bfloat16 hw = __float2bfloat16_rn(v.w);
            __nv_bfloat16 lx = __float2bfloat16_rn(v.x - __bfloat162float(hx));
            __nv_bfloat16 ly = __float2bfloat16_rn(v.y - __bfloat162float(hy));
            __nv_bfloat16 lz = __float2bfloat16_rn(v.z - __bfloat162float(hz));
            __nv_bfloat16 lw = __float2bfloat16_rn(v.w - __bfloat162float(hw));
            uint2 hp, lp;
            hp.x = ((uint32_t)__bfloat16_as_ushort(hy) << 16) | __bfloat16_as_ushort(hx);
            hp.y = ((uint32_t)__bfloat16_as_ushort(hw) << 16) | __bfloat16_as_ushort(hz);
            lp.x = ((uint32_t)__bfloat16_as_ushort(ly) << 16) | __bfloat16_as_ushort(lx);
            lp.y = ((uint32_t)__bfloat16_as_ushort(lw) << 16) | __bfloat16_as_ushort(lz);
            *(uint2*)(sAh + ldRow * PADK + ldCol + 4 * j) = hp;
            *(uint2*)(sAl + ldRow * PADK + ldCol + 4 * j) = lp;
        }
        // ---- W chunk (already bf16, [n][k]) ----
        const uint2* Wh = (const uint2*)(WtHi + ldRow * D + kc * BK + ldCol);
        const uint2* Wl = (const uint2*)(WtLo + ldRow * D + kc * BK + ldCol);
#pragma unroll
        for (int j = 0; j < 8; j++) {
            *(uint2*)(sWh + ldRow * PADK + ldCol + 4 * j) = Wh[j];
            *(uint2*)(sWl + ldRow * PADK + ldCol + 4 * j) = Wl[j];
        }
        __syncthreads();

        // ---- MMA over 4 k16-steps x 3 products ----
#pragma unroll
        for (int ks = 0; ks < 4; ks++) {
            int acol = ks * 16 + ((lane >> 4) << 3);
            int lrow = lane & 15;
#pragma unroll
            for (int p = 0; p < 3; p++) {
                uint32_t ab = (p == 2) ? aAl : aAh;
                uint32_t bb = (p == 1) ? aWl : aWh;
                uint32_t af[2][4];
                ldsm_x4(af[0], ab + (uint32_t)(((m0      + lrow) * PADK + acol) * 2));
                ldsm_x4(af[1], ab + (uint32_t)(((m0 + 16 + lrow) * PADK + acol) * 2));
                uint32_t bf_[4][4];
#pragma unroll
                for (int bt = 0; bt < 4; bt++)
                    ldsm_x4(bf_[bt], bb + (uint32_t)(((n0 + bt * 16 + lrow) * PADK + acol) * 2));
#pragma unroll
                for (int mt = 0; mt < 2; mt++)
#pragma unroll
                    for (int bt = 0; bt < 4; bt++) {
                        mma_bf16(acc[mt][2 * bt],     af[mt], bf_[bt][0], bf_[bt][2]);
                        mma_bf16(acc[mt][2 * bt + 1], af[mt], bf_[bt][1], bf_[bt][3]);
                    }
            }
        }
        __syncthreads();
    }

    // ---- epilogue: scale rows by dis, store ----
#pragma unroll
    for (int mt = 0; mt < 2; mt++) {
        int r0 = row0 + m0 + mt * 16 + (lane >> 2);
        int r1 = r0 + 8;
        float d0 = (r0 < n) ? g_dis[r0] : 0.f;
        float d1 = (r1 < n) ? g_dis[r1] : 0.f;
#pragma unroll
        for (int nt = 0; nt < 8; nt++) {
            int col = n0 + nt * 8 + (lane & 3) * 2;
            if (r0 < n) {
                float2 o = make_float2(acc[mt][nt][0] * d0, acc[mt][nt][1] * d0);
                *(float2*)(G + (size_t)r0 * D + col) = o;
            }
            if (r1 < n) {
                float2 o = make_float2(acc[mt][nt][2] * d1, acc[mt][nt][3] * d1);
                *(float2*)(G + (size_t)r1 * D + col) = o;
            }
        }
    }
}

// ---------------- neighbor aggregation (one warp per node) -------------------
__global__ void k_aggregate(const float* __restrict__ G,
                            const float* __restrict__ bias,
                            float* __restrict__ out, int n, int applyRelu) {
    int warp = (blockIdx.x * blockDim.x + threadIdx.x) >> 5;
    if (warp >= n) return;
    int lane = threadIdx.x & 31;

    const float4* G4 = (const float4*)G;
    float4 acc = G4[(size_t)warp * 32 + lane];    // self term
    int start = g_offsets[warp];
    int cnt   = g_counts[warp];

    int e = 0;
    for (; e + 4 <= cnt; e += 4) {
        int s0 = g_adj[start + e + 0];
        int s1 = g_adj[start + e + 1];
        int s2 = g_adj[start + e + 2];
        int s3 = g_adj[start + e + 3];
        float4 v0 = G4[(size_t)s0 * 32 + lane];
        float4 v1 = G4[(size_t)s1 * 32 + lane];
        float4 v2 = G4[(size_t)s2 * 32 + lane];
        float4 v3 = G4[(size_t)s3 * 32 + lane];
        acc.x += v0.x + v1.x + v2.x + v3.x;
        acc.y += v0.y + v1.y + v2.y + v3.y;
        acc.z += v0.z + v1.z + v2.z + v3.z;
        acc.w += v0.w + v1.w + v2.w + v3.w;
    }
    for (; e < cnt; e++) {
        int s = g_adj[start + e];
        float4 v = G4[(size_t)s * 32 + lane];
        acc.x += v.x; acc.y += v.y; acc.z += v.z; acc.w += v.w;
    }

    float ds = g_dis[warp];
    float4 b4 = ((const float4*)bias)[lane];
    float4 o;
    o.x = fmaf(ds, acc.x, b4.x);
    o.y = fmaf(ds, acc.y, b4.y);
    o.z = fmaf(ds, acc.z, b4.z);
    o.w = fmaf(ds, acc.w, b4.w);
    if (applyRelu) {
        o.x = fmaxf(o.x, 0.f); o.y = fmaxf(o.y, 0.f);
        o.z = fmaxf(o.z, 0.f); o.w = fmaxf(o.w, 0.f);
    }
    ((float4*)out)[(size_t)warp * 32 + lane] = o;
}

// ---------------- launch -----------------------------------------------------
extern "C" void kernel_launch(void* const* d_in, const int* in_sizes, int n_in,
                              void* d_out, int out_size) {
    const float* x  = (const float*)d_in[0];
    const int*   ei = (const int*)d_in[1];
    const float* W0 = (const float*)d_in[2];
    const float* b0 = (const float*)d_in[3];
    const float* W1 = (const float*)d_in[4];
    const float* b1 = (const float*)d_in[5];
    const float* W2 = (const float*)d_in[6];
    const float* b2 = (const float*)d_in[7];

    int n = in_sizes[0] / D;
    int e = in_sizes[1] / 2;
    const int* src = ei;
    const int* dst = ei + e;

    float* bufG = nullptr; float* bufH = nullptr;
    int* countsPtr = nullptr; int* cursorPtr = nullptr;
    __nv_bfloat16* wtHi = nullptr; __nv_bfloat16* wtLo = nullptr;
    cudaGetSymbolAddress((void**)&bufG, g_bufG);
    cudaGetSymbolAddress((void**)&bufH, g_bufH);
    cudaGetSymbolAddress((void**)&countsPtr, g_counts);
    cudaGetSymbolAddress((void**)&cursorPtr, g_cursor);
    cudaGetSymbolAddress((void**)&wtHi, g_WtHi);
    cudaGetSymbolAddress((void**)&wtLo, g_WtLo);
    float* out = (float*)d_out;

    cudaFuncSetAttribute(k_gemm_mma, cudaFuncAttributeMaxDynamicSharedMemorySize, GEMM_SMEM);

    int gn = (n + 255) / 256;
    int ge = (e + 255) / 256;
    int nb = (n + 1023) / 1024;

    cudaMemsetAsync(countsPtr, 0, (size_t)n * sizeof(int));
    cudaMemsetAsync(cursorPtr, 0, (size_t)n * sizeof(int));
    k_count<<<ge, 256>>>(dst, e);
    k_scan1<<<nb, 1024>>>(n);
    k_scan2<<<1, 32>>>(nb);
    k_scan3<<<gn, 256>>>(n);
    k_fill <<<ge, 256>>>(src, dst, e);
    k_prep_w<<<D, D>>>(W0, wtHi + 0 * D * D, wtLo + 0 * D * D);
    k_prep_w<<<D, D>>>(W1, wtHi + 1 * D * D, wtLo + 1 * D * D);
    k_prep_w<<<D, D>>>(W2, wtHi + 2 * D * D, wtLo + 2 * D * D);

    int ggemm = (n + 127) / 128;
    int gagg  = (n * 32 + 255) / 256;

    k_gemm_mma <<<ggemm, 256, GEMM_SMEM>>>(x, wtHi + 0 * D * D, wtLo + 0 * D * D, bufG, n);
    k_aggregate<<<gagg, 256>>>(bufG, b0, bufH, n, 1);
    k_gemm_mma <<<ggemm, 256, GEMM_SMEM>>>(bufH, wtHi + 1 * D * D, wtLo + 1 * D * D, bufG, n);
    k_aggregate<<<gagg, 256>>>(bufG, b1, bufH, n, 1);
    k_gemm_mma <<<ggemm, 256, GEMM_SMEM>>>(bufH, wtHi + 2 * D * D, wtLo + 2 * D * D, bufG, n);
    k_aggregate<<<gagg, 256>>>(bufG, b2, out, n, 0);
}

// round 5
// speedup vs baseline: 1.4899x; 1.0913x over previous
#include <cuda_runtime.h>
#include <cuda_bf16.h>
#include <cuda_fp16.h>
#include <math.h>
#include <stdint.h>

#define NMAX 50000
#define EMAX 800000
#define D 128

// ---------------- scratch (static device globals; no allocation) -------------
__device__ int   g_counts[NMAX];
__device__ int   g_offsets[NMAX];
__device__ int   g_cursor[NMAX];
__device__ int   g_bsums[256];
__device__ int   g_adj[EMAX];
__device__ float g_dis[NMAX];
__device__ __half g_bufG[NMAX * D];          // fp16 message buffer (gather side)
__device__ float g_bufH[NMAX * D];           // fp32 activations (GEMM input)
__device__ __nv_bfloat16 g_WtHi[3][D * D];   // W transposed [n][k], hi part
__device__ __nv_bfloat16 g_WtLo[3][D * D];   // residual lo part

// ---------------- PTX helpers (sm_80-era: mma.sync + ldmatrix) ---------------
__device__ __forceinline__ uint32_t smem_u32(const void* p) {
    uint32_t a;
    asm("{ .reg .u64 t; cvta.to.shared.u64 t, %1; cvt.u32.u64 %0, t; }" : "=r"(a) : "l"(p));
    return a;
}

__device__ __forceinline__ void ldsm_x4(uint32_t* r, uint32_t addr) {
    asm volatile("ldmatrix.sync.aligned.m8n8.x4.shared.b16 {%0,%1,%2,%3}, [%4];"
        : "=r"(r[0]), "=r"(r[1]), "=r"(r[2]), "=r"(r[3]) : "r"(addr));
}

__device__ __forceinline__ void mma_bf16(float* c, const uint32_t* a, uint32_t b0, uint32_t b1) {
    asm volatile(
        "mma.sync.aligned.m16n8k16.row.col.f32.bf16.bf16.f32 "
        "{%0,%1,%2,%3}, {%4,%5,%6,%7}, {%8,%9}, {%0,%1,%2,%3};"
        : "+f"(c[0]), "+f"(c[1]), "+f"(c[2]), "+f"(c[3])
        : "r"(a[0]), "r"(a[1]), "r"(a[2]), "r"(a[3]), "r"(b0), "r"(b1));
}

// ---------------- preprocessing ---------------------------------------------
__global__ void k_count(const int* __restrict__ dst, int e) {
    int i = blockIdx.x * blockDim.x + threadIdx.x;
    if (i < e) atomicAdd(&g_counts[dst[i]], 1);
}

__global__ void k_scan1(int n) {
    __shared__ int sh[1024];
    int i = blockIdx.x * 1024 + threadIdx.x;
    int v = (i < n) ? g_counts[i] : 0;
    if (i < n) g_dis[i] = rsqrtf((float)(v + 1));   // +1 self loop
    sh[threadIdx.x] = v;
    __syncthreads();
    for (int off = 1; off < 1024; off <<= 1) {
        int t = 0;
        if ((int)threadIdx.x >= off) t = sh[threadIdx.x - off];
        __syncthreads();
        sh[threadIdx.x] += t;
        __syncthreads();
    }
    if (i < n) g_offsets[i] = sh[threadIdx.x] - v;
    if (threadIdx.x == 1023) g_bsums[blockIdx.x] = sh[1023];
}

__global__ void k_scan2(int nb) {
    if (threadIdx.x == 0 && blockIdx.x == 0) {
        int run = 0;
        for (int b = 0; b < nb; b++) { int t = g_bsums[b]; g_bsums[b] = run; run += t; }
    }
}

__global__ void k_scan3(int n) {
    int i = blockIdx.x * blockDim.x + threadIdx.x;
    if (i < n) g_offsets[i] += g_bsums[i >> 10];
}

__global__ void k_fill(const int* __restrict__ src, const int* __restrict__ dst, int e) {
    int i = blockIdx.x * blockDim.x + threadIdx.x;
    if (i < e) {
        int d = dst[i];
        int p = atomicAdd(&g_cursor[d], 1);
        g_adj[g_offsets[d] + p] = src[i];
    }
}

// ---------------- W transpose + bf16 split (all 3 layers, one launch) --------
__global__ void k_prep_w(const float* __restrict__ W0,
                         const float* __restrict__ W1,
                         const float* __restrict__ W2) {
    int layer = blockIdx.y;
    const float* W = (layer == 0) ? W0 : (layer == 1) ? W1 : W2;
    int nn = blockIdx.x;
    int k  = threadIdx.x;
    float v = W[k * D + nn];
    __nv_bfloat16 h = __float2bfloat16_rn(v);
    __nv_bfloat16 l = __float2bfloat16_rn(v - __bfloat162float(h));
    g_WtHi[layer][nn * D + k] = h;
    g_WtLo[layer][nn * D + k] = l;
}

// ---------------- HMMA GEMM:  G(fp16) = diag(dis) * (A @ W) ------------------
// 128x128 block tile, 256 threads = 8 warps (4x2), warp tile 32x64.
// bf16 hi/lo split, 3 products: Ah@Wh + Ah@Wl + Al@Wh, fp32 accum.
#define BK   64
#define PADK 72
#define SM_TILE (128 * PADK)              // halves per tile
#define GEMM_SMEM (4 * SM_TILE * 2)       // bytes: Ah, Al, Wh, Wl

__global__ void __launch_bounds__(256, 2) k_gemm_mma(
    const float* __restrict__ A,
    const __nv_bfloat16* __restrict__ WtHi,
    const __nv_bfloat16* __restrict__ WtLo,
    __half* __restrict__ G, int n)
{
    extern __shared__ char smem[];
    __nv_bfloat16* sAh = (__nv_bfloat16*)smem;
    __nv_bfloat16* sAl = sAh + SM_TILE;
    __nv_bfloat16* sWh = sAl + SM_TILE;
    __nv_bfloat16* sWl = sWh + SM_TILE;

    int tid  = threadIdx.x;
    int lane = tid & 31;
    int w    = tid >> 5;
    int warp_m = w >> 1;
    int warp_n = w & 1;
    int m0 = warp_m * 32;
    int n0 = warp_n * 64;
    int row0 = blockIdx.x * 128;

    uint32_t aAh = smem_u32(sAh);
    uint32_t aAl = smem_u32(sAl);
    uint32_t aWh = smem_u32(sWh);
    uint32_t aWl = smem_u32(sWl);

    float acc[2][8][4];
#pragma unroll
    for (int mt = 0; mt < 2; mt++)
#pragma unroll
        for (int nt = 0; nt < 8; nt++)
#pragma unroll
            for (int q = 0; q < 4; q++) acc[mt][nt][q] = 0.f;

    int ldRow = tid >> 1;
    int ldCol = (tid & 1) * 32;

    for (int kc = 0; kc < 2; kc++) {
        bool okA = (row0 + ldRow) < n;
        const float4* Ar = (const float4*)(A + (size_t)(row0 + ldRow) * D + kc * BK + ldCol);
#pragma unroll
        for (int j = 0; j < 8; j++) {
            float4 v = okA ? Ar[j] : make_float4(0.f, 0.f, 0.f, 0.f);
            __nv_bfloat16 hx = __float2bfloat16_rn(v.x);
            __nv_bfloat16 hy = __float2bfloat16_rn(v.y);
            __nv_bfloat16 hz = __float2bfloat16_rn(v.z);
            __nv_bfloat16 hw = __float2bfloat16_rn(v.w);
            __nv_bfloat16 lx = __float2bfloat16_rn(v.x - __bfloat162float(hx));
            __nv_bfloat16 ly = __float2bfloat16_rn(v.y - __bfloat162float(hy));
            __nv_bfloat16 lz = __float2bfloat16_rn(v.z - __bfloat162float(hz));
            __nv_bfloat16 lw = __float2bfloat16_rn(v.w - __bfloat162float(hw));
            uint2 hp, lp;
            hp.x = ((uint32_t)__bfloat16_as_ushort(hy) << 16) | __bfloat16_as_ushort(hx);
            hp.y = ((uint32_t)__bfloat16_as_ushort(hw) << 16) | __bfloat16_as_ushort(hz);
            lp.x = ((uint32_t)__bfloat16_as_ushort(ly) << 16) | __bfloat16_as_ushort(lx);
            lp.y = ((uint32_t)__bfloat16_as_ushort(lw) << 16) | __bfloat16_as_ushort(lz);
            *(uint2*)(sAh + ldRow * PADK + ldCol + 4 * j) = hp;
            *(uint2*)(sAl + ldRow * PADK + ldCol + 4 * j) = lp;
        }
        const uint2* Wh = (const uint2*)(WtHi + ldRow * D + kc * BK + ldCol);
        const uint2* Wl = (const uint2*)(WtLo + ldRow * D + kc * BK + ldCol);
#pragma unroll
        for (int j = 0; j < 8; j++) {
            *(uint2*)(sWh + ldRow * PADK + ldCol + 4 * j) = Wh[j];
            *(uint2*)(sWl + ldRow * PADK + ldCol + 4 * j) = Wl[j];
        }
        __syncthreads();

#pragma unroll
        for (int ks = 0; ks < 4; ks++) {
            int acol = ks * 16 + ((lane >> 4) << 3);
            int lrow = lane & 15;
#pragma unroll
            for (int p = 0; p < 3; p++) {
                uint32_t ab = (p == 2) ? aAl : aAh;
                uint32_t bb = (p == 1) ? aWl : aWh;
                uint32_t af[2][4];
                ldsm_x4(af[0], ab + (uint32_t)(((m0      + lrow) * PADK + acol) * 2));
                ldsm_x4(af[1], ab + (uint32_t)(((m0 + 16 + lrow) * PADK + acol) * 2));
                uint32_t bf_[4][4];
#pragma unroll
                for (int bt = 0; bt < 4; bt++)
                    ldsm_x4(bf_[bt], bb + (uint32_t)(((n0 + bt * 16 + lrow) * PADK + acol) * 2));
#pragma unroll
                for (int mt = 0; mt < 2; mt++)
#pragma unroll
                    for (int bt = 0; bt < 4; bt++) {
                        mma_bf16(acc[mt][2 * bt],     af[mt], bf_[bt][0], bf_[bt][2]);
                        mma_bf16(acc[mt][2 * bt + 1], af[mt], bf_[bt][1], bf_[bt][3]);
                    }
            }
        }
        __syncthreads();
    }

    // ---- epilogue: scale rows by dis, store fp16 ----
#pragma unroll
    for (int mt = 0; mt < 2; mt++) {
        int r0 = row0 + m0 + mt * 16 + (lane >> 2);
        int r1 = r0 + 8;
        float d0 = (r0 < n) ? g_dis[r0] : 0.f;
        float d1 = (r1 < n) ? g_dis[r1] : 0.f;
#pragma unroll
        for (int nt = 0; nt < 8; nt++) {
            int col = n0 + nt * 8 + (lane & 3) * 2;
            if (r0 < n)
                *(__half2*)(G + (size_t)r0 * D + col) =
                    __floats2half2_rn(acc[mt][nt][0] * d0, acc[mt][nt][1] * d0);
            if (r1 < n)
                *(__half2*)(G + (size_t)r1 * D + col) =
                    __floats2half2_rn(acc[mt][nt][2] * d1, acc[mt][nt][3] * d1);
        }
    }
}

// ---------------- neighbor aggregation (one warp per node, fp16 gather) ------
// out[d] = dis[d] * ( sum_{s in adj(d)} g[s] + g[d] ) + b  [; relu]
__global__ void k_aggregate(const __half* __restrict__ G,
                            const float* __restrict__ bias,
                            float* __restrict__ out, int n, int applyRelu) {
    int warp = (blockIdx.x * blockDim.x + threadIdx.x) >> 5;
    if (warp >= n) return;
    int lane = threadIdx.x & 31;

    // row = 128 halves = 32 uint2; lane covers 4 halves (8B)
    const uint2* G8 = (const uint2*)G;

    uint2 sr = G8[(size_t)warp * 32 + lane];     // self term
    float2 s0 = __half22float2(*(const __half2*)&sr.x);
    float2 s1 = __half22float2(*(const __half2*)&sr.y);
    float4 acc = make_float4(s0.x, s0.y, s1.x, s1.y);

    int start = g_offsets[warp];
    int cnt   = g_counts[warp];

    int e = 0;
    for (; e + 4 <= cnt; e += 4) {
        int i0 = g_adj[start + e + 0];
        int i1 = g_adj[start + e + 1];
        int i2 = g_adj[start + e + 2];
        int i3 = g_adj[start + e + 3];
        uint2 r0 = G8[(size_t)i0 * 32 + lane];
        uint2 r1 = G8[(size_t)i1 * 32 + lane];
        uint2 r2 = G8[(size_t)i2 * 32 + lane];
        uint2 r3 = G8[(size_t)i3 * 32 + lane];
        float2 a, b;
        a = __half22float2(*(const __half2*)&r0.x); b = __half22float2(*(const __half2*)&r0.y);
        acc.x += a.x; acc.y += a.y; acc.z += b.x; acc.w += b.y;
        a = __half22float2(*(const __half2*)&r1.x); b = __half22float2(*(const __half2*)&r1.y);
        acc.x += a.x; acc.y += a.y; acc.z += b.x; acc.w += b.y;
        a = __half22float2(*(const __half2*)&r2.x); b = __half22float2(*(const __half2*)&r2.y);
        acc.x += a.x; acc.y += a.y; acc.z += b.x; acc.w += b.y;
        a = __half22float2(*(const __half2*)&r3.x); b = __half22float2(*(const __half2*)&r3.y);
        acc.x += a.x; acc.y += a.y; acc.z += b.x; acc.w += b.y;
    }
    for (; e < cnt; e++) {
        int s = g_adj[start + e];
        uint2 r = G8[(size_t)s * 32 + lane];
        float2 a = __half22float2(*(const __half2*)&r.x);
        float2 b = __half22float2(*(const __half2*)&r.y);
        acc.x += a.x; acc.y += a.y; acc.z += b.x; acc.w += b.y;
    }

    float ds = g_dis[warp];
    float4 b4 = ((const float4*)bias)[lane];
    float4 o;
    o.x = fmaf(ds, acc.x, b4.x);
    o.y = fmaf(ds, acc.y, b4.y);
    o.z = fmaf(ds, acc.z, b4.z);
    o.w = fmaf(ds, acc.w, b4.w);
    if (applyRelu) {
        o.x = fmaxf(o.x, 0.f); o.y = fmaxf(o.y, 0.f);
        o.z = fmaxf(o.z, 0.f); o.w = fmaxf(o.w, 0.f);
    }
    ((float4*)out)[(size_t)warp * 32 + lane] = o;
}

// ---------------- launch -----------------------------------------------------
extern "C" void kernel_launch(void* const* d_in, const int* in_sizes, int n_in,
                              void* d_out, int out_size) {
    const float* x  = (const float*)d_in[0];
    const int*   ei = (const int*)d_in[1];
    const float* W0 = (const float*)d_in[2];
    const float* b0 = (const float*)d_in[3];
    const float* W1 = (const float*)d_in[4];
    const float* b1 = (const float*)d_in[5];
    const float* W2 = (const float*)d_in[6];
    const float* b2 = (const float*)d_in[7];

    int n = in_sizes[0] / D;
    int e = in_sizes[1] / 2;
    const int* src = ei;
    const int* dst = ei + e;

    __half* bufG = nullptr; float* bufH = nullptr;
    int* countsPtr = nullptr; int* cursorPtr = nullptr;
    __nv_bfloat16* wtHi = nullptr; __nv_bfloat16* wtLo = nullptr;
    cudaGetSymbolAddress((void**)&bufG, g_bufG);
    cudaGetSymbolAddress((void**)&bufH, g_bufH);
    cudaGetSymbolAddress((void**)&countsPtr, g_counts);
    cudaGetSymbolAddress((void**)&cursorPtr, g_cursor);
    cudaGetSymbolAddress((void**)&wtHi, g_WtHi);
    cudaGetSymbolAddress((void**)&wtLo, g_WtLo);
    float* out = (float*)d_out;

    cudaFuncSetAttribute(k_gemm_mma, cudaFuncAttributeMaxDynamicSharedMemorySize, GEMM_SMEM);

    int gn = (n + 255) / 256;
    int ge = (e + 255) / 256;
    int nb = (n + 1023) / 1024;

    cudaMemsetAsync(countsPtr, 0, (size_t)n * sizeof(int));
    cudaMemsetAsync(cursorPtr, 0, (size_t)n * sizeof(int));
    k_count<<<ge, 256>>>(dst, e);
    k_scan1<<<nb, 1024>>>(n);
    k_scan2<<<1, 32>>>(nb);
    k_scan3<<<gn, 256>>>(n);
    k_fill <<<ge, 256>>>(src, dst, e);
    {
        dim3 gw(D, 3);
        k_prep_w<<<gw, D>>>(W0, W1, W2);
    }

    int ggemm = (n + 127) / 128;
    int gagg  = (n * 32 + 255) / 256;

    k_gemm_mma <<<ggemm, 256, GEMM_SMEM>>>(x, wtHi + 0 * D * D, wtLo + 0 * D * D, bufG, n);
    k_aggregate<<<gagg, 256>>>(bufG, b0, bufH, n, 1);
    k_gemm_mma <<<ggemm, 256, GEMM_SMEM>>>(bufH, wtHi + 1 * D * D, wtLo + 1 * D * D, bufG, n);
    k_aggregate<<<gagg, 256>>>(bufG, b1, bufH, n, 1);
    k_gemm_mma <<<ggemm, 256, GEMM_SMEM>>>(bufH, wtHi + 2 * D * D, wtLo + 2 * D * D, bufG, n);
    k_aggregate<<<gagg, 256>>>(bufG, b2, out, n, 0);
}